// round 3
// baseline (speedup 1.0000x reference)
#include <cuda_runtime.h>
#include <cuda_bf16.h>
#include <cstdint>

#define M_TOT 8192   // B*S
#define N_TOT 4096   // OUT
#define K_TOT 4096   // IN

// ---------------------------------------------------------------------------
// Scratch (device globals)
// ---------------------------------------------------------------------------
static __device__ int8_t        g_x1[(size_t)M_TOT * K_TOT];    // high plane
static __device__ int8_t        g_x0[(size_t)M_TOT * K_TOT];    // low plane
static __device__ __nv_bfloat16 g_xhi[(size_t)M_TOT * K_TOT];   // bf16(x)
static __device__ int8_t        g_base[(size_t)N_TOT * K_TOT];  // nib-8
static __device__ __nv_bfloat16 g_orth[(size_t)N_TOT * K_TOT];  // bf16(ortho)
static __device__ float         g_sx[M_TOT];                    // x row scales

// ---------------------------------------------------------------------------
// Prep 1: per-row quantize x -> s_m * (128*x1 + x0), and bf16(x).
// One block (128 thr) per row of 4096 floats.
// ---------------------------------------------------------------------------
__global__ void prep_x_q(const float* __restrict__ x) {
    const int row = blockIdx.x;
    const int t = threadIdx.x;
    const float4* xr = reinterpret_cast<const float4*>(x) + (size_t)row * 1024;

    float4 v[8];
    float amax = 0.0f;
#pragma unroll
    for (int i = 0; i < 8; i++) {
        v[i] = xr[t + i * 128];
        amax = fmaxf(amax, fmaxf(fmaxf(fabsf(v[i].x), fabsf(v[i].y)),
                                 fmaxf(fabsf(v[i].z), fabsf(v[i].w))));
    }
#pragma unroll
    for (int o = 16; o; o >>= 1) amax = fmaxf(amax, __shfl_xor_sync(~0u, amax, o));
    __shared__ float red[4];
    __shared__ float s_bc;
    if ((t & 31) == 0) red[t >> 5] = amax;
    __syncthreads();
    if (t == 0) {
        float m = fmaxf(fmaxf(red[0], red[1]), fmaxf(red[2], red[3]));
        s_bc = m;
        g_sx[row] = m * (1.0f / 16256.0f);
    }
    __syncthreads();
    const float inv = 16256.0f / s_bc;

    uint32_t* p1 = reinterpret_cast<uint32_t*>(g_x1) + (size_t)row * 1024;
    uint32_t* p0 = reinterpret_cast<uint32_t*>(g_x0) + (size_t)row * 1024;
    uint2* ph = reinterpret_cast<uint2*>(g_xhi) + (size_t)row * 1024;
#pragma unroll
    for (int i = 0; i < 8; i++) {
        float f[4] = {v[i].x, v[i].y, v[i].z, v[i].w};
        uint32_t b1 = 0, b0 = 0;
        uint32_t h01, h23;
#pragma unroll
        for (int j = 0; j < 4; j++) {
            float qp = f[j] * inv;
            float hq = rintf(qp * 0.0078125f);   // /128
            float q = rintf(qp);
            int i1 = (int)hq;
            int i0 = (int)(q - 128.0f * hq);
            b1 |= ((uint32_t)i1 & 0xFFu) << (8 * j);
            b0 |= ((uint32_t)i0 & 0xFFu) << (8 * j);
        }
        __nv_bfloat16 h0 = __float2bfloat16_rn(f[0]);
        __nv_bfloat16 h1 = __float2bfloat16_rn(f[1]);
        __nv_bfloat16 h2 = __float2bfloat16_rn(f[2]);
        __nv_bfloat16 h3 = __float2bfloat16_rn(f[3]);
        h01 = (uint32_t)__bfloat16_as_ushort(h0) | ((uint32_t)__bfloat16_as_ushort(h1) << 16);
        h23 = (uint32_t)__bfloat16_as_ushort(h2) | ((uint32_t)__bfloat16_as_ushort(h3) << 16);
        p1[t + i * 128] = b1;
        p0[t + i * 128] = b0;
        ph[t + i * 128] = make_uint2(h01, h23);
    }
}

// ---------------------------------------------------------------------------
// Prep 2a: unpack int4 base -> int8 (nib - 8). One thread: 4 packed ints.
// ---------------------------------------------------------------------------
__global__ void prep_base(const int* __restrict__ packed) {
    size_t t = (size_t)blockIdx.x * blockDim.x + threadIdx.x;
    if (t >= ((size_t)N_TOT * (K_TOT / 2)) / 4) return;
    int4 p = reinterpret_cast<const int4*>(packed)[t];
    int pv[4] = {p.x, p.y, p.z, p.w};
    uint32_t w0 = 0, w1 = 0;
#pragma unroll
    for (int q = 0; q < 4; q++) {
        int lo = (pv[q] & 0xF) - 8;
        int hi = ((pv[q] >> 4) & 0xF) - 8;
        uint32_t& dst = (q < 2) ? w0 : w1;
        int sh = (q & 1) * 16;
        dst |= ((uint32_t)lo & 0xFFu) << sh;
        dst |= ((uint32_t)hi & 0xFFu) << (sh + 8);
    }
    reinterpret_cast<uint2*>(g_base)[t] = make_uint2(w0, w1);
}

// ---------------------------------------------------------------------------
// Prep 2b: ortho fp32 -> bf16 (no scaling). One thread: 8 floats.
// ---------------------------------------------------------------------------
__global__ void prep_orth(const float* __restrict__ ortho) {
    size_t i = (size_t)blockIdx.x * blockDim.x + threadIdx.x;
    if (i >= ((size_t)N_TOT * K_TOT) / 8) return;
    const float4* ov = reinterpret_cast<const float4*>(ortho);
    float4 a = ov[i * 2 + 0];
    float4 b = ov[i * 2 + 1];
    float f[8] = {a.x, a.y, a.z, a.w, b.x, b.y, b.z, b.w};
    uint32_t w[4];
#pragma unroll
    for (int q = 0; q < 4; q++) {
        __nv_bfloat16 u0 = __float2bfloat16_rn(f[2 * q + 0]);
        __nv_bfloat16 u1 = __float2bfloat16_rn(f[2 * q + 1]);
        w[q] = (uint32_t)__bfloat16_as_ushort(u0) | ((uint32_t)__bfloat16_as_ushort(u1) << 16);
    }
    reinterpret_cast<uint4*>(g_orth)[i] = make_uint4(w[0], w[1], w[2], w[3]);
}

// ---------------------------------------------------------------------------
// Shared helpers
// ---------------------------------------------------------------------------
__device__ __forceinline__ void cp16(uint32_t dst, const void* src) {
    asm volatile("cp.async.cg.shared.global [%0], [%1], 16;" ::"r"(dst), "l"(src));
}
// 128-row x 128-byte tile, SW128-like xor swizzle; 256 threads participate.
// stride_b = gmem row stride in BYTES.
__device__ __forceinline__ void load_tile(uint32_t tb, const char* src,
                                          size_t stride_b, int c, int r0) {
#pragma unroll
    for (int i = 0; i < 4; i++) {
        int row = r0 + i * 32;
        cp16(tb + row * 128 + (((uint32_t)(c ^ (row & 7))) << 4),
             src + (size_t)row * stride_b + c * 16);
    }
}
// L2-friendly block swizzle: bands of 8 M-blocks x 32 N-blocks.
__device__ __forceinline__ void block_coords(int& bm, int& bn) {
    int gid = blockIdx.x;
    int band = gid >> 8;
    int rem = gid & 255;
    bm = ((band << 3) + (rem & 7)) * 128;
    bn = (rem >> 3) * 128;
}

// ---------------------------------------------------------------------------
// GEMM 1 (bf16): out[m][n] = xhi . orth^T   (plain write, no scaling)
// Tile 128x128, BK=64 bf16 (128B rows), 3-stage cp.async, 8 warps (2x4).
// ---------------------------------------------------------------------------
#define BF_STAGE 32768
__global__ void __launch_bounds__(256, 2)
gemm_bf16_orth(float* __restrict__ out) {
    extern __shared__ char smem_raw[];
    uint32_t S = (uint32_t)__cvta_generic_to_shared(smem_raw);
    const int tid = threadIdx.x;
    const int lane = tid & 31;
    const int warp = tid >> 5;
    const int wm = warp >> 2;
    const int wn = warp & 3;
    int bm, bn;
    block_coords(bm, bn);

    const int c = tid & 7;
    const int r0 = tid >> 3;
    const char* Ab = (const char*)(g_xhi + (size_t)bm * K_TOT);
    const char* Bb = (const char*)(g_orth + (size_t)bn * K_TOT);

    float acc[4][4][4];
#pragma unroll
    for (int a = 0; a < 4; a++)
#pragma unroll
        for (int b = 0; b < 4; b++)
#pragma unroll
            for (int d = 0; d < 4; d++) acc[a][b][d] = 0.0f;

    const int NCH = K_TOT / 64;  // 64
    auto load_stage = [&](int s) {
        uint32_t base = S + (s % 3) * BF_STAGE;
        load_tile(base, Ab + (size_t)s * 128, K_TOT * 2, c, r0);
        load_tile(base + 16384, Bb + (size_t)s * 128, K_TOT * 2, c, r0);
    };
    load_stage(0);
    asm volatile("cp.async.commit_group;");
    load_stage(1);
    asm volatile("cp.async.commit_group;");

    for (int t = 0; t < NCH; ++t) {
        asm volatile("cp.async.wait_group 1;");
        __syncthreads();
        if (t + 2 < NCH) load_stage(t + 2);
        asm volatile("cp.async.commit_group;");

        uint32_t aBase = S + (t % 3) * BF_STAGE;
        uint32_t bBase = aBase + 16384;
#pragma unroll
        for (int ks = 0; ks < 4; ++ks) {
            uint32_t af[4][4];
            uint32_t bfm[4][2];
            const int chunk = ks * 2 + (lane >> 4);
            const int lrow = lane & 15;
#pragma unroll
            for (int mi = 0; mi < 4; mi++) {
                int row = wm * 64 + mi * 16 + lrow;
                uint32_t addr = aBase + row * 128 + (((uint32_t)(chunk ^ (row & 7))) << 4);
                asm volatile(
                    "ldmatrix.sync.aligned.m8n8.x4.shared.b16 {%0,%1,%2,%3}, [%4];"
                    : "=r"(af[mi][0]), "=r"(af[mi][1]), "=r"(af[mi][2]), "=r"(af[mi][3])
                    : "r"(addr));
            }
#pragma unroll
            for (int np = 0; np < 2; np++) {
                int row = wn * 32 + np * 16 + lrow;
                uint32_t addr = bBase + row * 128 + (((uint32_t)(chunk ^ (row & 7))) << 4);
                uint32_t q0, q1, q2, q3;
                asm volatile(
                    "ldmatrix.sync.aligned.m8n8.x4.shared.b16 {%0,%1,%2,%3}, [%4];"
                    : "=r"(q0), "=r"(q1), "=r"(q2), "=r"(q3)
                    : "r"(addr));
                bfm[np * 2 + 0][0] = q0; bfm[np * 2 + 0][1] = q2;
                bfm[np * 2 + 1][0] = q1; bfm[np * 2 + 1][1] = q3;
            }
#pragma unroll
            for (int mi = 0; mi < 4; mi++)
#pragma unroll
                for (int nt = 0; nt < 4; nt++) {
                    asm volatile(
                        "mma.sync.aligned.m16n8k16.row.col.f32.bf16.bf16.f32 "
                        "{%0,%1,%2,%3}, {%4,%5,%6,%7}, {%8,%9}, {%0,%1,%2,%3};"
                        : "+f"(acc[mi][nt][0]), "+f"(acc[mi][nt][1]),
                          "+f"(acc[mi][nt][2]), "+f"(acc[mi][nt][3])
                        : "r"(af[mi][0]), "r"(af[mi][1]), "r"(af[mi][2]), "r"(af[mi][3]),
                          "r"(bfm[nt][0]), "r"(bfm[nt][1]));
                }
        }
    }

#pragma unroll
    for (int nt = 0; nt < 4; nt++) {
        int col = bn + wn * 32 + nt * 8 + (lane & 3) * 2;
#pragma unroll
        for (int mi = 0; mi < 4; mi++) {
            int row = bm + wm * 64 + mi * 16 + (lane >> 2);
            float2* p0 = reinterpret_cast<float2*>(out + (size_t)row * N_TOT + col);
            float2* p1 = reinterpret_cast<float2*>(out + (size_t)(row + 8) * N_TOT + col);
            *p0 = make_float2(acc[mi][nt][0], acc[mi][nt][1]);
            *p1 = make_float2(acc[mi][nt][2], acc[mi][nt][3]);
        }
    }
}

// ---------------------------------------------------------------------------
// GEMM 2 (int8 dual-plane, RMW):
//   out[m][n] += sx[m]*scale[n]*(128*(x1.base^T) + (x0.base^T))
// Tile 128x128, BK=128 int8 (128B rows), 3-stage, imma m16n8k32.
// ---------------------------------------------------------------------------
#define I8_STAGE 49152
__global__ void __launch_bounds__(256, 1)
gemm_i8_base(float* __restrict__ out, const float* __restrict__ scales) {
    extern __shared__ char smem_raw[];
    uint32_t S = (uint32_t)__cvta_generic_to_shared(smem_raw);
    const int tid = threadIdx.x;
    const int lane = tid & 31;
    const int warp = tid >> 5;
    const int wm = warp >> 2;
    const int wn = warp & 3;
    int bm, bn;
    block_coords(bm, bn);

    const int c = tid & 7;
    const int r0 = tid >> 3;
    const char* A1b = (const char*)(g_x1 + (size_t)bm * K_TOT);
    const char* A0b = (const char*)(g_x0 + (size_t)bm * K_TOT);
    const char* Bb = (const char*)(g_base + (size_t)bn * K_TOT);

    int acc1[4][4][4], acc0[4][4][4];
#pragma unroll
    for (int a = 0; a < 4; a++)
#pragma unroll
        for (int b = 0; b < 4; b++)
#pragma unroll
            for (int d = 0; d < 4; d++) { acc1[a][b][d] = 0; acc0[a][b][d] = 0; }

    const int NST = K_TOT / 128;  // 32
    auto load_stage = [&](int s) {
        uint32_t base = S + (s % 3) * I8_STAGE;
        load_tile(base, A1b + (size_t)s * 128, K_TOT, c, r0);
        load_tile(base + 16384, A0b + (size_t)s * 128, K_TOT, c, r0);
        load_tile(base + 32768, Bb + (size_t)s * 128, K_TOT, c, r0);
    };
    load_stage(0);
    asm volatile("cp.async.commit_group;");
    load_stage(1);
    asm volatile("cp.async.commit_group;");

    for (int t = 0; t < NST; ++t) {
        asm volatile("cp.async.wait_group 1;");
        __syncthreads();
        if (t + 2 < NST) load_stage(t + 2);
        asm volatile("cp.async.commit_group;");

        uint32_t a1Base = S + (t % 3) * I8_STAGE;
        uint32_t a0Base = a1Base + 16384;
        uint32_t bBase = a1Base + 32768;
#pragma unroll
        for (int ks = 0; ks < 4; ++ks) {  // each ks = k32 (32 bytes = 2 chunks)
            const int chunk = ks * 2 + (lane >> 4);
            const int lrow = lane & 15;
            uint32_t bfm[4][2];
#pragma unroll
            for (int np = 0; np < 2; np++) {
                int row = wn * 32 + np * 16 + lrow;
                uint32_t addr = bBase + row * 128 + (((uint32_t)(chunk ^ (row & 7))) << 4);
                uint32_t q0, q1, q2, q3;
                asm volatile(
                    "ldmatrix.sync.aligned.m8n8.x4.shared.b16 {%0,%1,%2,%3}, [%4];"
                    : "=r"(q0), "=r"(q1), "=r"(q2), "=r"(q3)
                    : "r"(addr));
                bfm[np * 2 + 0][0] = q0; bfm[np * 2 + 0][1] = q2;
                bfm[np * 2 + 1][0] = q1; bfm[np * 2 + 1][1] = q3;
            }
            uint32_t af[4][4];
#pragma unroll
            for (int mi = 0; mi < 4; mi++) {
                int row = wm * 64 + mi * 16 + lrow;
                uint32_t addr = a1Base + row * 128 + (((uint32_t)(chunk ^ (row & 7))) << 4);
                asm volatile(
                    "ldmatrix.sync.aligned.m8n8.x4.shared.b16 {%0,%1,%2,%3}, [%4];"
                    : "=r"(af[mi][0]), "=r"(af[mi][1]), "=r"(af[mi][2]), "=r"(af[mi][3])
                    : "r"(addr));
            }
#pragma unroll
            for (int mi = 0; mi < 4; mi++)
#pragma unroll
                for (int nt = 0; nt < 4; nt++) {
                    asm volatile(
                        "mma.sync.aligned.m16n8k32.row.col.s32.s8.s8.s32 "
                        "{%0,%1,%2,%3}, {%4,%5,%6,%7}, {%8,%9}, {%0,%1,%2,%3};"
                        : "+r"(acc1[mi][nt][0]), "+r"(acc1[mi][nt][1]),
                          "+r"(acc1[mi][nt][2]), "+r"(acc1[mi][nt][3])
                        : "r"(af[mi][0]), "r"(af[mi][1]), "r"(af[mi][2]), "r"(af[mi][3]),
                          "r"(bfm[nt][0]), "r"(bfm[nt][1]));
                }
#pragma unroll
            for (int mi = 0; mi < 4; mi++) {
                int row = wm * 64 + mi * 16 + lrow;
                uint32_t addr = a0Base + row * 128 + (((uint32_t)(chunk ^ (row & 7))) << 4);
                asm volatile(
                    "ldmatrix.sync.aligned.m8n8.x4.shared.b16 {%0,%1,%2,%3}, [%4];"
                    : "=r"(af[mi][0]), "=r"(af[mi][1]), "=r"(af[mi][2]), "=r"(af[mi][3])
                    : "r"(addr));
            }
#pragma unroll
            for (int mi = 0; mi < 4; mi++)
#pragma unroll
                for (int nt = 0; nt < 4; nt++) {
                    asm volatile(
                        "mma.sync.aligned.m16n8k32.row.col.s32.s8.s8.s32 "
                        "{%0,%1,%2,%3}, {%4,%5,%6,%7}, {%8,%9}, {%0,%1,%2,%3};"
                        : "+r"(acc0[mi][nt][0]), "+r"(acc0[mi][nt][1]),
                          "+r"(acc0[mi][nt][2]), "+r"(acc0[mi][nt][3])
                        : "r"(af[mi][0]), "r"(af[mi][1]), "r"(af[mi][2]), "r"(af[mi][3]),
                          "r"(bfm[nt][0]), "r"(bfm[nt][1]));
                }
        }
    }

    // epilogue: out += sx[m]*scale[n]*(128*acc1+acc0)
#pragma unroll
    for (int nt = 0; nt < 4; nt++) {
        int col = bn + wn * 32 + nt * 8 + (lane & 3) * 2;
        float s0 = __ldg(&scales[col]);
        float s1 = __ldg(&scales[col + 1]);
#pragma unroll
        for (int mi = 0; mi < 4; mi++) {
            int row = bm + wm * 64 + mi * 16 + (lane >> 2);
            float sm0 = g_sx[row];
            float sm1 = g_sx[row + 8];
            float2* p0 = reinterpret_cast<float2*>(out + (size_t)row * N_TOT + col);
            float2* p1 = reinterpret_cast<float2*>(out + (size_t)(row + 8) * N_TOT + col);
            float2 o0 = *p0;
            float2 o1 = *p1;
            o0.x += (float)(128 * acc1[mi][nt][0] + acc0[mi][nt][0]) * sm0 * s0;
            o0.y += (float)(128 * acc1[mi][nt][1] + acc0[mi][nt][1]) * sm0 * s1;
            o1.x += (float)(128 * acc1[mi][nt][2] + acc0[mi][nt][2]) * sm1 * s0;
            o1.y += (float)(128 * acc1[mi][nt][3] + acc0[mi][nt][3]) * sm1 * s1;
            *p0 = o0;
            *p1 = o1;
        }
    }
}

// ---------------------------------------------------------------------------
// Launch
// ---------------------------------------------------------------------------
extern "C" void kernel_launch(void* const* d_in, const int* in_sizes, int n_in,
                              void* d_out, int out_size) {
    const float* x      = (const float*)d_in[0];
    const int*   packed = (const int*)d_in[1];
    const float* scales = (const float*)d_in[2];
    const float* ortho  = (const float*)d_in[3];
    float* out = (float*)d_out;

    prep_x_q<<<M_TOT, 128>>>(x);
    prep_base<<<((size_t)N_TOT * (K_TOT / 2) / 4 + 255) / 256, 256>>>(packed);
    prep_orth<<<((size_t)N_TOT * K_TOT / 8 + 255) / 256, 256>>>(ortho);

    cudaFuncSetAttribute(gemm_bf16_orth, cudaFuncAttributeMaxDynamicSharedMemorySize,
                         3 * BF_STAGE);
    gemm_bf16_orth<<<(M_TOT / 128) * (N_TOT / 128), 256, 3 * BF_STAGE>>>(out);

    cudaFuncSetAttribute(gemm_i8_base, cudaFuncAttributeMaxDynamicSharedMemorySize,
                         3 * I8_STAGE);
    gemm_i8_base<<<(M_TOT / 128) * (N_TOT / 128), 256, 3 * I8_STAGE>>>(out, scales);
}

// round 4
// speedup vs baseline: 5.9692x; 5.9692x over previous
#include <cuda_runtime.h>
#include <cuda_fp16.h>
#include <cstdint>

#define M_TOT 8192   // B*S
#define N_TOT 4096   // OUT
#define K_TOT 4096   // IN

// ---------------------------------------------------------------------------
// Scratch (device globals)
//  g_xh : fp16(x)                                    [M, K]
//  g_w  : fp16( (nib-8) + ortho/scale )              [N, K]
//  out  = (g_xh . g_w^T) * scale[n]
//  Note: 95% of g_w entries are exact small integers in fp16; x rounding
//  (2^-12 rms) dominates the error -> predicted rel_err ~2e-4.
// ---------------------------------------------------------------------------
static __device__ __half g_xh[(size_t)M_TOT * K_TOT];
static __device__ __half g_w[(size_t)N_TOT * K_TOT];

// ---------------------------------------------------------------------------
// Prep 1: x fp32 -> fp16. One thread: 8 floats.
// ---------------------------------------------------------------------------
__global__ void prep_x(const float* __restrict__ x) {
    size_t i = (size_t)blockIdx.x * blockDim.x + threadIdx.x;
    if (i >= ((size_t)M_TOT * K_TOT) / 8) return;
    const float4* xv = reinterpret_cast<const float4*>(x);
    float4 a = xv[i * 2 + 0];
    float4 b = xv[i * 2 + 1];
    float f[8] = {a.x, a.y, a.z, a.w, b.x, b.y, b.z, b.w};
    uint32_t w[4];
#pragma unroll
    for (int q = 0; q < 4; q++) {
        __half h0 = __float2half_rn(f[2 * q + 0]);
        __half h1 = __float2half_rn(f[2 * q + 1]);
        w[q] = (uint32_t)__half_as_ushort(h0) | ((uint32_t)__half_as_ushort(h1) << 16);
    }
    reinterpret_cast<uint4*>(g_xh)[i] = make_uint4(w[0], w[1], w[2], w[3]);
}

// ---------------------------------------------------------------------------
// Prep 2: W = (nib-8) + ortho/scale, fp16. One thread: 4 packed ints = 8 w.
// ---------------------------------------------------------------------------
__global__ void prep_w(const int* __restrict__ packed,
                       const float* __restrict__ scales,
                       const float* __restrict__ ortho) {
    size_t t = (size_t)blockIdx.x * blockDim.x + threadIdx.x;
    if (t >= ((size_t)N_TOT * (K_TOT / 2)) / 4) return;
    int o = (int)(t >> 9);   // 512 groups of 8 weights per output row
    int jj = (int)(t & 511);

    int4 p = reinterpret_cast<const int4*>(packed)[t];
    float inv = 1.0f / __ldg(&scales[o]);
    const float4* orow =
        reinterpret_cast<const float4*>(ortho + (size_t)o * K_TOT + (size_t)jj * 8);
    float4 t0 = orow[0];
    float4 t1 = orow[1];
    float og[8] = {t0.x, t0.y, t0.z, t0.w, t1.x, t1.y, t1.z, t1.w};
    int pv[4] = {p.x, p.y, p.z, p.w};

    uint32_t w[4];
#pragma unroll
    for (int q = 0; q < 4; q++) {
        float w0 = (float)((pv[q] & 0xF) - 8)        + og[2 * q + 0] * inv;
        float w1 = (float)(((pv[q] >> 4) & 0xF) - 8) + og[2 * q + 1] * inv;
        __half h0 = __float2half_rn(w0);
        __half h1 = __float2half_rn(w1);
        w[q] = (uint32_t)__half_as_ushort(h0) | ((uint32_t)__half_as_ushort(h1) << 16);
    }
    reinterpret_cast<uint4*>(g_w)[t] = make_uint4(w[0], w[1], w[2], w[3]);
}

// ---------------------------------------------------------------------------
// Helpers
// ---------------------------------------------------------------------------
__device__ __forceinline__ void cp16(uint32_t dst, const void* src) {
    asm volatile("cp.async.cg.shared.global [%0], [%1], 16;" ::"r"(dst), "l"(src));
}
// 128-row x 128-byte tile, xor swizzle; 256 threads participate.
__device__ __forceinline__ void load_tile(uint32_t tb, const char* src,
                                          size_t stride_b, int c, int r0) {
#pragma unroll
    for (int i = 0; i < 4; i++) {
        int row = r0 + i * 32;
        cp16(tb + row * 128 + (((uint32_t)(c ^ (row & 7))) << 4),
             src + (size_t)row * stride_b + c * 16);
    }
}
// L2-friendly block swizzle: bands of 8 M-blocks x 32 N-blocks.
__device__ __forceinline__ void block_coords(int& bm, int& bn) {
    int gid = blockIdx.x;
    int band = gid >> 8;
    int rem = gid & 255;
    bm = ((band << 3) + (rem & 7)) * 128;
    bn = (rem >> 3) * 128;
}

// ---------------------------------------------------------------------------
// GEMM (fp16 HMMA): out[m][n] = scale[n] * (xh . w^T)
// Tile 128x128, BK=64 fp16 (128B rows), 3-stage cp.async, 8 warps (2x4).
// ---------------------------------------------------------------------------
#define BF_STAGE 32768
__global__ void __launch_bounds__(256, 2)
gemm_f16(float* __restrict__ out, const float* __restrict__ scales) {
    extern __shared__ char smem_raw[];
    uint32_t S = (uint32_t)__cvta_generic_to_shared(smem_raw);
    const int tid = threadIdx.x;
    const int lane = tid & 31;
    const int warp = tid >> 5;
    const int wm = warp >> 2;
    const int wn = warp & 3;
    int bm, bn;
    block_coords(bm, bn);

    const int c = tid & 7;
    const int r0 = tid >> 3;
    const char* Ab = (const char*)(g_xh + (size_t)bm * K_TOT);
    const char* Bb = (const char*)(g_w + (size_t)bn * K_TOT);

    float acc[4][4][4];
#pragma unroll
    for (int a = 0; a < 4; a++)
#pragma unroll
        for (int b = 0; b < 4; b++)
#pragma unroll
            for (int d = 0; d < 4; d++) acc[a][b][d] = 0.0f;

    const int NCH = K_TOT / 64;  // 64
    auto load_stage = [&](int s) {
        uint32_t base = S + (s % 3) * BF_STAGE;
        load_tile(base, Ab + (size_t)s * 128, K_TOT * 2, c, r0);
        load_tile(base + 16384, Bb + (size_t)s * 128, K_TOT * 2, c, r0);
    };
    load_stage(0);
    asm volatile("cp.async.commit_group;");
    load_stage(1);
    asm volatile("cp.async.commit_group;");

    for (int t = 0; t < NCH; ++t) {
        asm volatile("cp.async.wait_group 1;");
        __syncthreads();
        if (t + 2 < NCH) load_stage(t + 2);
        asm volatile("cp.async.commit_group;");

        uint32_t aBase = S + (t % 3) * BF_STAGE;
        uint32_t bBase = aBase + 16384;
#pragma unroll
        for (int ks = 0; ks < 4; ++ks) {
            uint32_t af[4][4];
            uint32_t bfm[4][2];
            const int chunk = ks * 2 + (lane >> 4);
            const int lrow = lane & 15;
#pragma unroll
            for (int mi = 0; mi < 4; mi++) {
                int row = wm * 64 + mi * 16 + lrow;
                uint32_t addr = aBase + row * 128 + (((uint32_t)(chunk ^ (row & 7))) << 4);
                asm volatile(
                    "ldmatrix.sync.aligned.m8n8.x4.shared.b16 {%0,%1,%2,%3}, [%4];"
                    : "=r"(af[mi][0]), "=r"(af[mi][1]), "=r"(af[mi][2]), "=r"(af[mi][3])
                    : "r"(addr));
            }
#pragma unroll
            for (int np = 0; np < 2; np++) {
                int row = wn * 32 + np * 16 + lrow;
                uint32_t addr = bBase + row * 128 + (((uint32_t)(chunk ^ (row & 7))) << 4);
                uint32_t q0, q1, q2, q3;
                asm volatile(
                    "ldmatrix.sync.aligned.m8n8.x4.shared.b16 {%0,%1,%2,%3}, [%4];"
                    : "=r"(q0), "=r"(q1), "=r"(q2), "=r"(q3)
                    : "r"(addr));
                bfm[np * 2 + 0][0] = q0; bfm[np * 2 + 0][1] = q2;
                bfm[np * 2 + 1][0] = q1; bfm[np * 2 + 1][1] = q3;
            }
#pragma unroll
            for (int mi = 0; mi < 4; mi++)
#pragma unroll
                for (int nt = 0; nt < 4; nt++) {
                    asm volatile(
                        "mma.sync.aligned.m16n8k16.row.col.f32.f16.f16.f32 "
                        "{%0,%1,%2,%3}, {%4,%5,%6,%7}, {%8,%9}, {%0,%1,%2,%3};"
                        : "+f"(acc[mi][nt][0]), "+f"(acc[mi][nt][1]),
                          "+f"(acc[mi][nt][2]), "+f"(acc[mi][nt][3])
                        : "r"(af[mi][0]), "r"(af[mi][1]), "r"(af[mi][2]), "r"(af[mi][3]),
                          "r"(bfm[nt][0]), "r"(bfm[nt][1]));
                }
        }
    }

    // epilogue: out = acc * scale[n]
#pragma unroll
    for (int nt = 0; nt < 4; nt++) {
        int col = bn + wn * 32 + nt * 8 + (lane & 3) * 2;
        float s0 = __ldg(&scales[col]);
        float s1 = __ldg(&scales[col + 1]);
#pragma unroll
        for (int mi = 0; mi < 4; mi++) {
            int row = bm + wm * 64 + mi * 16 + (lane >> 2);
            float2* p0 = reinterpret_cast<float2*>(out + (size_t)row * N_TOT + col);
            float2* p1 = reinterpret_cast<float2*>(out + (size_t)(row + 8) * N_TOT + col);
            *p0 = make_float2(acc[mi][nt][0] * s0, acc[mi][nt][1] * s1);
            *p1 = make_float2(acc[mi][nt][2] * s0, acc[mi][nt][3] * s1);
        }
    }
}

// ---------------------------------------------------------------------------
// Launch
// ---------------------------------------------------------------------------
extern "C" void kernel_launch(void* const* d_in, const int* in_sizes, int n_in,
                              void* d_out, int out_size) {
    const float* x      = (const float*)d_in[0];
    const int*   packed = (const int*)d_in[1];
    const float* scales = (const float*)d_in[2];
    const float* ortho  = (const float*)d_in[3];
    float* out = (float*)d_out;

    prep_x<<<((size_t)M_TOT * K_TOT / 8 + 255) / 256, 256>>>(x);
    prep_w<<<((size_t)N_TOT * (K_TOT / 2) / 4 + 255) / 256, 256>>>(packed, scales, ortho);

    cudaFuncSetAttribute(gemm_f16, cudaFuncAttributeMaxDynamicSharedMemorySize,
                         3 * BF_STAGE);
    gemm_f16<<<(M_TOT / 128) * (N_TOT / 128), 256, 3 * BF_STAGE>>>(out, scales);
}

// round 5
// speedup vs baseline: 5.9730x; 1.0006x over previous
#include <cuda_runtime.h>
#include <cuda_fp16.h>
#include <cstdint>

#define M_TOT 8192   // B*S
#define N_TOT 4096   // OUT
#define K_TOT 4096   // IN

// ---------------------------------------------------------------------------
// Scratch (device globals)
//  g_xh : fp16(x)                                    [M, K]
//  g_w  : fp16( (nib-8) + ortho/scale )              [N, K]
//  out  = (g_xh . g_w^T) * scale[n]
//  Note: 95% of g_w entries are exact small integers in fp16; x rounding
//  (2^-12 rms) dominates the error -> predicted rel_err ~2e-4.
// ---------------------------------------------------------------------------
static __device__ __half g_xh[(size_t)M_TOT * K_TOT];
static __device__ __half g_w[(size_t)N_TOT * K_TOT];

// ---------------------------------------------------------------------------
// Prep 1: x fp32 -> fp16. One thread: 8 floats.
// ---------------------------------------------------------------------------
__global__ void prep_x(const float* __restrict__ x) {
    size_t i = (size_t)blockIdx.x * blockDim.x + threadIdx.x;
    if (i >= ((size_t)M_TOT * K_TOT) / 8) return;
    const float4* xv = reinterpret_cast<const float4*>(x);
    float4 a = xv[i * 2 + 0];
    float4 b = xv[i * 2 + 1];
    float f[8] = {a.x, a.y, a.z, a.w, b.x, b.y, b.z, b.w};
    uint32_t w[4];
#pragma unroll
    for (int q = 0; q < 4; q++) {
        __half h0 = __float2half_rn(f[2 * q + 0]);
        __half h1 = __float2half_rn(f[2 * q + 1]);
        w[q] = (uint32_t)__half_as_ushort(h0) | ((uint32_t)__half_as_ushort(h1) << 16);
    }
    reinterpret_cast<uint4*>(g_xh)[i] = make_uint4(w[0], w[1], w[2], w[3]);
}

// ---------------------------------------------------------------------------
// Prep 2: W = (nib-8) + ortho/scale, fp16. One thread: 4 packed ints = 8 w.
// ---------------------------------------------------------------------------
__global__ void prep_w(const int* __restrict__ packed,
                       const float* __restrict__ scales,
                       const float* __restrict__ ortho) {
    size_t t = (size_t)blockIdx.x * blockDim.x + threadIdx.x;
    if (t >= ((size_t)N_TOT * (K_TOT / 2)) / 4) return;
    int o = (int)(t >> 9);   // 512 groups of 8 weights per output row
    int jj = (int)(t & 511);

    int4 p = reinterpret_cast<const int4*>(packed)[t];
    float inv = 1.0f / __ldg(&scales[o]);
    const float4* orow =
        reinterpret_cast<const float4*>(ortho + (size_t)o * K_TOT + (size_t)jj * 8);
    float4 t0 = orow[0];
    float4 t1 = orow[1];
    float og[8] = {t0.x, t0.y, t0.z, t0.w, t1.x, t1.y, t1.z, t1.w};
    int pv[4] = {p.x, p.y, p.z, p.w};

    uint32_t w[4];
#pragma unroll
    for (int q = 0; q < 4; q++) {
        float w0 = (float)((pv[q] & 0xF) - 8)        + og[2 * q + 0] * inv;
        float w1 = (float)(((pv[q] >> 4) & 0xF) - 8) + og[2 * q + 1] * inv;
        __half h0 = __float2half_rn(w0);
        __half h1 = __float2half_rn(w1);
        w[q] = (uint32_t)__half_as_ushort(h0) | ((uint32_t)__half_as_ushort(h1) << 16);
    }
    reinterpret_cast<uint4*>(g_w)[t] = make_uint4(w[0], w[1], w[2], w[3]);
}

// ---------------------------------------------------------------------------
// Helpers
// ---------------------------------------------------------------------------
__device__ __forceinline__ void cp16(uint32_t dst, const void* src) {
    asm volatile("cp.async.cg.shared.global [%0], [%1], 16;" ::"r"(dst), "l"(src));
}
// 128-row x 128-byte tile, xor swizzle; 256 threads participate.
__device__ __forceinline__ void load_tile(uint32_t tb, const char* src,
                                          size_t stride_b, int c, int r0) {
#pragma unroll
    for (int i = 0; i < 4; i++) {
        int row = r0 + i * 32;
        cp16(tb + row * 128 + (((uint32_t)(c ^ (row & 7))) << 4),
             src + (size_t)row * stride_b + c * 16);
    }
}
// L2-friendly block swizzle: bands of 8 M-blocks x 32 N-blocks.
__device__ __forceinline__ void block_coords(int& bm, int& bn) {
    int gid = blockIdx.x;
    int band = gid >> 8;
    int rem = gid & 255;
    bm = ((band << 3) + (rem & 7)) * 128;
    bn = (rem >> 3) * 128;
}

// ---------------------------------------------------------------------------
// GEMM (fp16 HMMA): out[m][n] = scale[n] * (xh . w^T)
// Tile 128x128, BK=64 fp16 (128B rows), 3-stage cp.async, 8 warps (2x4).
// ---------------------------------------------------------------------------
#define BF_STAGE 32768
__global__ void __launch_bounds__(256, 2)
gemm_f16(float* __restrict__ out, const float* __restrict__ scales) {
    extern __shared__ char smem_raw[];
    uint32_t S = (uint32_t)__cvta_generic_to_shared(smem_raw);
    const int tid = threadIdx.x;
    const int lane = tid & 31;
    const int warp = tid >> 5;
    const int wm = warp >> 2;
    const int wn = warp & 3;
    int bm, bn;
    block_coords(bm, bn);

    const int c = tid & 7;
    const int r0 = tid >> 3;
    const char* Ab = (const char*)(g_xh + (size_t)bm * K_TOT);
    const char* Bb = (const char*)(g_w + (size_t)bn * K_TOT);

    float acc[4][4][4];
#pragma unroll
    for (int a = 0; a < 4; a++)
#pragma unroll
        for (int b = 0; b < 4; b++)
#pragma unroll
            for (int d = 0; d < 4; d++) acc[a][b][d] = 0.0f;

    const int NCH = K_TOT / 64;  // 64
    auto load_stage = [&](int s) {
        uint32_t base = S + (s % 3) * BF_STAGE;
        load_tile(base, Ab + (size_t)s * 128, K_TOT * 2, c, r0);
        load_tile(base + 16384, Bb + (size_t)s * 128, K_TOT * 2, c, r0);
    };
    load_stage(0);
    asm volatile("cp.async.commit_group;");
    load_stage(1);
    asm volatile("cp.async.commit_group;");

    for (int t = 0; t < NCH; ++t) {
        asm volatile("cp.async.wait_group 1;");
        __syncthreads();
        if (t + 2 < NCH) load_stage(t + 2);
        asm volatile("cp.async.commit_group;");

        uint32_t aBase = S + (t % 3) * BF_STAGE;
        uint32_t bBase = aBase + 16384;
#pragma unroll
        for (int ks = 0; ks < 4; ++ks) {
            uint32_t af[4][4];
            uint32_t bfm[4][2];
            const int chunk = ks * 2 + (lane >> 4);
            const int lrow = lane & 15;
#pragma unroll
            for (int mi = 0; mi < 4; mi++) {
                int row = wm * 64 + mi * 16 + lrow;
                uint32_t addr = aBase + row * 128 + (((uint32_t)(chunk ^ (row & 7))) << 4);
                asm volatile(
                    "ldmatrix.sync.aligned.m8n8.x4.shared.b16 {%0,%1,%2,%3}, [%4];"
                    : "=r"(af[mi][0]), "=r"(af[mi][1]), "=r"(af[mi][2]), "=r"(af[mi][3])
                    : "r"(addr));
            }
#pragma unroll
            for (int np = 0; np < 2; np++) {
                int row = wn * 32 + np * 16 + lrow;
                uint32_t addr = bBase + row * 128 + (((uint32_t)(chunk ^ (row & 7))) << 4);
                uint32_t q0, q1, q2, q3;
                asm volatile(
                    "ldmatrix.sync.aligned.m8n8.x4.shared.b16 {%0,%1,%2,%3}, [%4];"
                    : "=r"(q0), "=r"(q1), "=r"(q2), "=r"(q3)
                    : "r"(addr));
                bfm[np * 2 + 0][0] = q0; bfm[np * 2 + 0][1] = q2;
                bfm[np * 2 + 1][0] = q1; bfm[np * 2 + 1][1] = q3;
            }
#pragma unroll
            for (int mi = 0; mi < 4; mi++)
#pragma unroll
                for (int nt = 0; nt < 4; nt++) {
                    asm volatile(
                        "mma.sync.aligned.m16n8k16.row.col.f32.f16.f16.f32 "
                        "{%0,%1,%2,%3}, {%4,%5,%6,%7}, {%8,%9}, {%0,%1,%2,%3};"
                        : "+f"(acc[mi][nt][0]), "+f"(acc[mi][nt][1]),
                          "+f"(acc[mi][nt][2]), "+f"(acc[mi][nt][3])
                        : "r"(af[mi][0]), "r"(af[mi][1]), "r"(af[mi][2]), "r"(af[mi][3]),
                          "r"(bfm[nt][0]), "r"(bfm[nt][1]));
                }
        }
    }

    // epilogue: out = acc * scale[n]
#pragma unroll
    for (int nt = 0; nt < 4; nt++) {
        int col = bn + wn * 32 + nt * 8 + (lane & 3) * 2;
        float s0 = __ldg(&scales[col]);
        float s1 = __ldg(&scales[col + 1]);
#pragma unroll
        for (int mi = 0; mi < 4; mi++) {
            int row = bm + wm * 64 + mi * 16 + (lane >> 2);
            float2* p0 = reinterpret_cast<float2*>(out + (size_t)row * N_TOT + col);
            float2* p1 = reinterpret_cast<float2*>(out + (size_t)(row + 8) * N_TOT + col);
            *p0 = make_float2(acc[mi][nt][0] * s0, acc[mi][nt][1] * s1);
            *p1 = make_float2(acc[mi][nt][2] * s0, acc[mi][nt][3] * s1);
        }
    }
}

// ---------------------------------------------------------------------------
// Launch
// ---------------------------------------------------------------------------
extern "C" void kernel_launch(void* const* d_in, const int* in_sizes, int n_in,
                              void* d_out, int out_size) {
    const float* x      = (const float*)d_in[0];
    const int*   packed = (const int*)d_in[1];
    const float* scales = (const float*)d_in[2];
    const float* ortho  = (const float*)d_in[3];
    float* out = (float*)d_out;

    prep_x<<<((size_t)M_TOT * K_TOT / 8 + 255) / 256, 256>>>(x);
    prep_w<<<((size_t)N_TOT * (K_TOT / 2) / 4 + 255) / 256, 256>>>(packed, scales, ortho);

    cudaFuncSetAttribute(gemm_f16, cudaFuncAttributeMaxDynamicSharedMemorySize,
                         3 * BF_STAGE);
    gemm_f16<<<(M_TOT / 128) * (N_TOT / 128), 256, 3 * BF_STAGE>>>(out, scales);
}